// round 1
// baseline (speedup 1.0000x reference)
#include <cuda_runtime.h>
#include <cstdint>
#include <cstddef>

// Problem constants
#define N_TOKENS 16384
#define EMB      2048
#define USR      256
#define KDIM     2304     // EMB + USR
#define NEXP     64
#define TOPK     8

// Tiling
#define KT       64       // K tile
#define NT       (KDIM / KT)   // 36 tiles
#define TB       64       // tokens per block
#define THREADS  256
#define XPAD     68       // x row stride in floats (keeps 16B alignment, spreads banks)

#define SMEM_FLOATS (2*KT*NEXP + 2*TB*XPAD)
#define SMEM_BYTES  (SMEM_FLOATS * 4)

// ---- packed fp32x2 FMA (sm_103a FFMA2; PTX-only) ----
__device__ __forceinline__ unsigned long long fma2(unsigned long long a,
                                                   unsigned long long b,
                                                   unsigned long long c) {
    unsigned long long d;
    asm("fma.rn.f32x2 %0, %1, %2, %3;" : "=l"(d) : "l"(a), "l"(b), "l"(c));
    return d;
}
__device__ __forceinline__ unsigned long long dup2(float x) {
    unsigned long long d;
    unsigned xi = __float_as_uint(x);
    asm("mov.b64 %0, {%1, %1};" : "=l"(d) : "r"(xi));
    return d;
}

__global__ __launch_bounds__(THREADS, 2)
void gate_kernel(const float* __restrict__ h, const float* __restrict__ u,
                 const float* __restrict__ W, const float* __restrict__ b,
                 float* __restrict__ out)
{
    extern __shared__ float smem[];
    float* Wsm = smem;                    // [2][KT][NEXP]
    float* Xsm = smem + 2 * KT * NEXP;    // [2][TB][XPAD]

    const int tid  = threadIdx.x;
    const int warp = tid >> 5;
    const int lane = tid & 31;
    const int tok0 = blockIdx.x * TB;

    // staging mapping: thread -> (row, 16-float column group)
    const int sr = tid >> 2;           // 0..63
    const int sc = (tid & 3) << 4;     // 0,16,32,48

    auto prefetch = [&](int T, int buf) {
        // W tile: rows T*KT .. T*KT+63, direct copy
        const float* wsrc = W + (size_t)(T * KT + sr) * NEXP + sc;
        unsigned wdst = (unsigned)__cvta_generic_to_shared(&Wsm[(buf * KT + sr) * NEXP + sc]);
        #pragma unroll
        for (int j = 0; j < 4; j++)
            asm volatile("cp.async.cg.shared.global [%0], [%1], 16;"
                         :: "r"(wdst + j * 16), "l"(wsrc + j * 4));
        // X tile: token rows, columns T*KT .. +63 (from h or u)
        const int kb = T * KT;
        const float* xsrc = (kb < EMB)
            ? (h + (size_t)(tok0 + sr) * EMB + kb + sc)
            : (u + (size_t)(tok0 + sr) * USR + (kb - EMB) + sc);
        unsigned xdst = (unsigned)__cvta_generic_to_shared(&Xsm[(buf * TB + sr) * XPAD + sc]);
        #pragma unroll
        for (int j = 0; j < 4; j++)
            asm volatile("cp.async.cg.shared.global [%0], [%1], 16;"
                         :: "r"(xdst + j * 16), "l"(xsrc + j * 4));
        asm volatile("cp.async.commit_group;");
    };

    unsigned long long acc[8];
    #pragma unroll
    for (int t = 0; t < 8; t++) acc[t] = 0ULL;

    prefetch(0, 0);

    for (int T = 0; T < NT; T++) {
        const int buf = T & 1;
        if (T + 1 < NT) {
            prefetch(T + 1, buf ^ 1);          // writes the buffer freed at end of iter T-1
            asm volatile("cp.async.wait_group 1;");
        } else {
            asm volatile("cp.async.wait_group 0;");
        }
        __syncthreads();

        const float* ws = Wsm + buf * KT * NEXP;
        const float* xs = Xsm + (buf * TB + warp * 8) * XPAD;

        #pragma unroll 4
        for (int kg = 0; kg < KT; kg += 4) {
            // W pairs for this lane's 2 experts, 4 consecutive k  (LDS.64, conflict-free)
            unsigned long long w0 = *(const unsigned long long*)&ws[(kg + 0) * NEXP + lane * 2];
            unsigned long long w1 = *(const unsigned long long*)&ws[(kg + 1) * NEXP + lane * 2];
            unsigned long long w2 = *(const unsigned long long*)&ws[(kg + 2) * NEXP + lane * 2];
            unsigned long long w3 = *(const unsigned long long*)&ws[(kg + 3) * NEXP + lane * 2];
            #pragma unroll
            for (int t = 0; t < 8; t++) {
                float4 xv = *(const float4*)&xs[t * XPAD + kg];   // warp-broadcast
                acc[t] = fma2(dup2(xv.x), w0, acc[t]);
                acc[t] = fma2(dup2(xv.y), w1, acc[t]);
                acc[t] = fma2(dup2(xv.z), w2, acc[t]);
                acc[t] = fma2(dup2(xv.w), w3, acc[t]);
            }
        }
        __syncthreads();
    }

    // ---- epilogue: bias + softmax + top-8 + renormalize, per token within warp ----
    const float b0 = b[lane * 2];
    const float b1 = b[lane * 2 + 1];

    #pragma unroll 1
    for (int t = 0; t < 8; t++) {
        unsigned lo_, hi_;
        asm("mov.b64 {%0, %1}, %2;" : "=r"(lo_), "=r"(hi_) : "l"(acc[t]));
        float v0 = __uint_as_float(lo_) + b0;
        float v1 = __uint_as_float(hi_) + b1;

        // softmax over 64 logits (2 per lane)
        float m = fmaxf(v0, v1);
        #pragma unroll
        for (int o = 16; o > 0; o >>= 1)
            m = fmaxf(m, __shfl_xor_sync(0xffffffffu, m, o));
        float e0 = expf(v0 - m);
        float e1 = expf(v1 - m);
        float s = e0 + e1;
        #pragma unroll
        for (int o = 16; o > 0; o >>= 1)
            s += __shfl_xor_sync(0xffffffffu, s, o);
        float p0 = e0 / s;
        float p1 = e1 / s;

        // greedy top-8 by (value desc, index asc) — matches jax.lax.top_k
        float c0 = p0, c1 = p1;
        float ssum = 0.0f;
        bool  s0 = false, s1 = false;
        #pragma unroll 1
        for (int it = 0; it < TOPK; it++) {
            float mv; int mi;
            if (c0 >= c1) { mv = c0; mi = lane * 2; }     // >= : lower index wins on tie
            else          { mv = c1; mi = lane * 2 + 1; }
            #pragma unroll
            for (int o = 16; o > 0; o >>= 1) {
                float ov = __shfl_xor_sync(0xffffffffu, mv, o);
                int   oi = __shfl_xor_sync(0xffffffffu, mi, o);
                if (ov > mv || (ov == mv && oi < mi)) { mv = ov; mi = oi; }
            }
            ssum += mv;
            if (mi == lane * 2)     { s0 = true; c0 = -1.0f; }
            if (mi == lane * 2 + 1) { s1 = true; c1 = -1.0f; }
        }

        const float inv = 1.0f / (ssum + 1e-9f);   // reference's exact +1e-9
        float2 o2;
        o2.x = s0 ? p0 * inv : 0.0f;
        o2.y = s1 ? p1 * inv : 0.0f;
        *(float2*)&out[(size_t)(tok0 + warp * 8 + t) * NEXP + lane * 2] = o2;
    }
}

extern "C" void kernel_launch(void* const* d_in, const int* in_sizes, int n_in,
                              void* d_out, int out_size) {
    const float* h = (const float*)d_in[0];
    const float* u = (const float*)d_in[1];
    const float* W = (const float*)d_in[2];
    const float* b = (const float*)d_in[3];
    float* out = (float*)d_out;

    cudaFuncSetAttribute(gate_kernel, cudaFuncAttributeMaxDynamicSharedMemorySize, SMEM_BYTES);
    gate_kernel<<<N_TOKENS / TB, THREADS, SMEM_BYTES>>>(h, u, W, b, out);
}

// round 4
// speedup vs baseline: 1.6314x; 1.6314x over previous
#include <cuda_runtime.h>
#include <cuda_bf16.h>
#include <cstdint>
#include <cstddef>

#define NTOK    16384
#define EMB     2048
#define USR     256
#define KDIM    2304
#define NEXP    64
#define TOPK    8
#define KC      64
#define NCHUNK  (KDIM / KC)     // 36
#define MTILE   128
#define THREADS 256
#define TAU     1e-4f

// padded row stride: 72 bf16 = 144 bytes (conflict-free ldmatrix, no swizzle)
#define RSTR    72
#define RSTRB   144

#define APART   18432
#define BPART   9216
#define OFF_B   (4 * APART)                 // 73728
#define SMEM_TOT (OFF_B + 4 * BPART)        // 110592

// prepacked W image: [chunk][part hi/lo][64 rows x 72 bf16]
__device__ __align__(16) __nv_bfloat16 g_wpack[NCHUNK][2][NEXP * RSTR];
// fp32 transposed W for exact fixup dots: [expert][k]
__device__ __align__(16) float g_wt[NEXP][KDIM];
// flagged-token records
#define FIXCAP NTOK
__device__ int   g_cnt;
__device__ int   g_tok[FIXCAP];
__device__ float g_w89[FIXCAP][2];
__device__ float g_prob[FIXCAP][NEXP];

// ---------- helpers ----------
__device__ __forceinline__ uint32_t smem_u32(const void* p) {
    uint32_t a;
    asm("{ .reg .u64 t; cvta.to.shared.u64 t, %1; cvt.u32.u64 %0, t; }" : "=r"(a) : "l"(p));
    return a;
}
__device__ __forceinline__ uint32_t cvt_bf16x2(float hi, float lo) {
    uint32_t r;
    asm("cvt.rn.bf16x2.f32 %0, %1, %2;" : "=r"(r) : "f"(hi), "f"(lo));
    return r;
}
__device__ __forceinline__ void sts64(uint32_t a, uint32_t r0, uint32_t r1) {
    asm volatile("st.shared.v2.b32 [%0], {%1, %2};" :: "r"(a), "r"(r0), "r"(r1) : "memory");
}
__device__ __forceinline__ void sts128(uint32_t a, uint4 v) {
    asm volatile("st.shared.v4.b32 [%0], {%1,%2,%3,%4};" :: "r"(a), "r"(v.x), "r"(v.y), "r"(v.z), "r"(v.w) : "memory");
}
__device__ __forceinline__ uint4 lds128(uint32_t a) {
    uint4 v;
    asm volatile("ld.shared.v4.b32 {%0,%1,%2,%3}, [%4];" : "=r"(v.x), "=r"(v.y), "=r"(v.z), "=r"(v.w) : "r"(a));
    return v;
}
__device__ __forceinline__ void ldsm4(uint32_t* r, uint32_t addr) {
    asm volatile("ldmatrix.sync.aligned.m8n8.x4.shared.b16 {%0,%1,%2,%3}, [%4];"
                 : "=r"(r[0]), "=r"(r[1]), "=r"(r[2]), "=r"(r[3]) : "r"(addr));
}
__device__ __forceinline__ void mma16816(float* d, const uint32_t* a, uint32_t b0, uint32_t b1) {
    asm volatile("mma.sync.aligned.m16n8k16.row.col.f32.bf16.bf16.f32 "
                 "{%0,%1,%2,%3}, {%4,%5,%6,%7}, {%8,%9}, {%0,%1,%2,%3};"
                 : "+f"(d[0]), "+f"(d[1]), "+f"(d[2]), "+f"(d[3])
                 : "r"(a[0]), "r"(a[1]), "r"(a[2]), "r"(a[3]), "r"(b0), "r"(b1));
}
__device__ __forceinline__ void cpasync16(uint32_t dst, const void* src) {
    asm volatile("cp.async.cg.shared.global [%0], [%1], 16;" :: "r"(dst), "l"(src));
}

// ---------- prep 1: split W into bf16 hi/lo, [n][k] rows padded to 144B ----------
__global__ void prep_w(const float* __restrict__ W) {
    int idx = blockIdx.x * blockDim.x + threadIdx.x;
    if (idx >= NCHUNK * NEXP * RSTR) return;
    int c   = idx / (NEXP * RSTR);
    int rem = idx % (NEXP * RSTR);
    int n   = rem / RSTR;
    int kk  = rem % RSTR;
    float v = (kk < KC) ? W[(size_t)(c * KC + kk) * NEXP + n] : 0.0f;
    __nv_bfloat16 hi = __float2bfloat16(v);
    __nv_bfloat16 lo = __float2bfloat16(v - __bfloat162float(hi));
    g_wpack[c][0][n * RSTR + kk] = hi;
    g_wpack[c][1][n * RSTR + kk] = lo;
}
// ---------- prep 2: fp32 transposed W + zero flag counter ----------
__global__ void prep_wt(const float* __restrict__ W) {
    int idx = blockIdx.x * blockDim.x + threadIdx.x;
    if (idx == 0) g_cnt = 0;
    if (idx >= NEXP * KDIM) return;
    int e = idx / KDIM;
    int k = idx % KDIM;
    g_wt[e][k] = W[(size_t)k * NEXP + e];
}

// ---------- main ----------
__global__ __launch_bounds__(THREADS, 1)
void gate_main(const float* __restrict__ hmat, const float* __restrict__ umat,
               const float* __restrict__ bias, float* __restrict__ out)
{
    extern __shared__ char smem[];
    const uint32_t sbase = smem_u32(smem);
    const int tid  = threadIdx.x;
    const int wid  = tid >> 5;
    const int lane = tid & 31;
    const int wr   = wid & 3;
    const int wc   = wid >> 2;
    const int tok0 = blockIdx.x * MTILE;

    const int r  = tid >> 1;
    const int k0 = (tid & 1) * 32;

    float4 xr[8];

    auto ldgA = [&](int c) {
        const int kb = c * KC;
        const float* src = (kb < EMB)
            ? hmat + (size_t)(tok0 + r) * EMB + kb + k0
            : umat + (size_t)(tok0 + r) * USR + (kb - EMB) + k0;
        #pragma unroll
        for (int j = 0; j < 8; j++) xr[j] = __ldg((const float4*)src + j);
    };
    auto cpB = [&](int c, int buf) {
        const char* src = (const char*)&g_wpack[c][0][0];
        const uint32_t dst = sbase + OFF_B + buf * (2 * BPART);
        #pragma unroll
        for (int i = tid; i < 2 * BPART / 16; i += THREADS)
            cpasync16(dst + i * 16, src + i * 16);
        asm volatile("cp.async.commit_group;");
    };
    auto convA = [&](int buf) {
        const uint32_t ah = sbase + (buf * 2 + 0) * APART;
        const uint32_t al = sbase + (buf * 2 + 1) * APART;
        #pragma unroll
        for (int j = 0; j < 8; j++) {
            float4 v = xr[j];
            uint32_t hi01 = cvt_bf16x2(v.y, v.x);
            uint32_t hi23 = cvt_bf16x2(v.w, v.z);
            float h0 = __uint_as_float(hi01 << 16);
            float h1 = __uint_as_float(hi01 & 0xFFFF0000u);
            float h2 = __uint_as_float(hi23 << 16);
            float h3 = __uint_as_float(hi23 & 0xFFFF0000u);
            uint32_t lo01 = cvt_bf16x2(v.y - h1, v.x - h0);
            uint32_t lo23 = cvt_bf16x2(v.w - h3, v.z - h2);
            unsigned off = (unsigned)(r * RSTRB + (k0 + 4 * j) * 2);
            sts64(ah + off, hi01, hi23);
            sts64(al + off, lo01, lo23);
        }
    };

    float acc[2][4][4];
    #pragma unroll
    for (int mt = 0; mt < 2; mt++)
        #pragma unroll
        for (int nt = 0; nt < 4; nt++)
            #pragma unroll
            for (int q = 0; q < 4; q++) acc[mt][nt][q] = 0.0f;

    const int arow = wr * 32 + ((lane >> 3) & 1) * 8 + (lane & 7);
    const int aoff = arow * RSTRB + (lane >> 4) * 16;
    const int bn   = wc * 32 + (lane >> 4) * 8 + (lane & 7);
    const int boff = bn * RSTRB + ((lane >> 3) & 1) * 16;

    ldgA(0);
    cpB(0, 0);

    for (int T = 0; T < NCHUNK; T++) {
        const int buf = T & 1;
        convA(buf);
        if (T + 1 < NCHUNK) ldgA(T + 1);
        asm volatile("cp.async.wait_group 0;");
        __syncthreads();
        if (T + 1 < NCHUNK) cpB(T + 1, buf ^ 1);

        const uint32_t ah = sbase + (buf * 2 + 0) * APART;
        const uint32_t al = sbase + (buf * 2 + 1) * APART;
        const uint32_t bh = sbase + OFF_B + buf * (2 * BPART);
        const uint32_t bl = bh + BPART;

        #pragma unroll
        for (int kt = 0; kt < 4; kt++) {
            const int kb = kt * 32;
            uint32_t Ah[2][4], Al[2][4], Bh[2][4], Bl[2][4];
            ldsm4(Ah[0], ah + aoff + kb);
            ldsm4(Ah[1], ah + aoff + kb + 16 * RSTRB);
            ldsm4(Al[0], al + aoff + kb);
            ldsm4(Al[1], al + aoff + kb + 16 * RSTRB);
            ldsm4(Bh[0], bh + boff + kb);
            ldsm4(Bh[1], bh + boff + kb + 16 * RSTRB);
            ldsm4(Bl[0], bl + boff + kb);
            ldsm4(Bl[1], bl + boff + kb + 16 * RSTRB);
            #pragma unroll
            for (int mt = 0; mt < 2; mt++) {
                mma16816(acc[mt][0], Ah[mt], Bh[0][0], Bh[0][1]);
                mma16816(acc[mt][1], Ah[mt], Bh[0][2], Bh[0][3]);
                mma16816(acc[mt][2], Ah[mt], Bh[1][0], Bh[1][1]);
                mma16816(acc[mt][3], Ah[mt], Bh[1][2], Bh[1][3]);
                mma16816(acc[mt][0], Ah[mt], Bl[0][0], Bl[0][1]);
                mma16816(acc[mt][1], Ah[mt], Bl[0][2], Bl[0][3]);
                mma16816(acc[mt][2], Ah[mt], Bl[1][0], Bl[1][1]);
                mma16816(acc[mt][3], Ah[mt], Bl[1][2], Bl[1][3]);
                mma16816(acc[mt][0], Al[mt], Bh[0][0], Bh[0][1]);
                mma16816(acc[mt][1], Al[mt], Bh[0][2], Bh[0][3]);
                mma16816(acc[mt][2], Al[mt], Bh[1][0], Bh[1][1]);
                mma16816(acc[mt][3], Al[mt], Bh[1][2], Bh[1][3]);
            }
        }
        __syncthreads();
    }

    // ---- epilogue ----
    const int t4r = lane >> 2;
    const int t4c = (lane & 3) * 2;
    #pragma unroll
    for (int mt = 0; mt < 2; mt++)
        #pragma unroll
        for (int nt = 0; nt < 4; nt++) {
            int row = wr * 32 + mt * 16 + t4r;
            int col = wc * 32 + nt * 8 + t4c;
            uint32_t a0 = sbase + (row * 68 + col) * 4;
            uint32_t a1 = sbase + ((row + 8) * 68 + col) * 4;
            sts64(a0, __float_as_uint(acc[mt][nt][0]), __float_as_uint(acc[mt][nt][1]));
            sts64(a1, __float_as_uint(acc[mt][nt][2]), __float_as_uint(acc[mt][nt][3]));
        }
    __syncthreads();

    if (tid < MTILE) {
        const int m = tid;
        float v[64];
        float mx = -3.4e38f;
        #pragma unroll
        for (int i = 0; i < 64; i++) {
            float lv;
            asm volatile("ld.shared.f32 %0, [%1];" : "=f"(lv) : "r"(sbase + (m * 68 + i) * 4));
            v[i] = lv + __ldg(&bias[i]);
            mx = fmaxf(mx, v[i]);
        }
        float s = 0.0f;
        #pragma unroll
        for (int i = 0; i < 64; i++) { v[i] = __expf(v[i] - mx); s += v[i]; }
        const float invs = 1.0f / s;
        #pragma unroll
        for (int i = 0; i < 64; i++) v[i] *= invs;

        // top-8 by (value desc, index asc)
        float prevV = 3.4e38f; int prevI = -1;
        float ssum = 0.0f;
        unsigned long long msk = 0ull;
        #pragma unroll 1
        for (int it = 0; it < TOPK; it++) {
            float bv = -1.0f; int bi = 64;
            #pragma unroll
            for (int i = 0; i < 64; i++) {
                bool elig = (v[i] < prevV) || (v[i] == prevV && i > prevI);
                bool bett = (v[i] > bv) || (v[i] == bv && i < bi);
                if (elig && bett) { bv = v[i]; bi = i; }
            }
            ssum += bv; prevV = bv; prevI = bi; msk |= 1ull << bi;
        }
        // 9th-largest for boundary-gap flagging
        float bv9 = -1.0f;
        {
            int bi9 = 64;
            #pragma unroll
            for (int i = 0; i < 64; i++) {
                bool elig = (v[i] < prevV) || (v[i] == prevV && i > prevI);
                bool bett = (v[i] > bv9) || (v[i] == bv9 && i < bi9);
                if (elig && bett) { bv9 = v[i]; bi9 = i; }
            }
        }
        if (prevV - bv9 < TAU) {
            int slot = atomicAdd(&g_cnt, 1);
            g_tok[slot] = tok0 + m;
            g_w89[slot][0] = prevV;   // 8th
            g_w89[slot][1] = bv9;     // 9th
            #pragma unroll
            for (int i = 0; i < 64; i++) g_prob[slot][i] = v[i];
        }

        const float inv = 1.0f / (ssum + 1e-9f);
        const uint32_t rowb = sbase + OFF_B + m * 256;
        #pragma unroll
        for (int j = 0; j < 16; j++) {
            float4 o;
            o.x = ((msk >> (4 * j + 0)) & 1) ? v[4 * j + 0] * inv : 0.0f;
            o.y = ((msk >> (4 * j + 1)) & 1) ? v[4 * j + 1] * inv : 0.0f;
            o.z = ((msk >> (4 * j + 2)) & 1) ? v[4 * j + 2] * inv : 0.0f;
            o.w = ((msk >> (4 * j + 3)) & 1) ? v[4 * j + 3] * inv : 0.0f;
            uint4 u4 = make_uint4(__float_as_uint(o.x), __float_as_uint(o.y),
                                  __float_as_uint(o.z), __float_as_uint(o.w));
            sts128(rowb + ((j ^ (m & 15)) * 16), u4);
        }
    }
    __syncthreads();

    {
        uint4* og = (uint4*)(out + (size_t)tok0 * NEXP);
        #pragma unroll
        for (int i = 0; i < 8; i++) {
            int f  = tid + THREADS * i;
            int rr = f >> 4, jj = f & 15;
            og[f] = lds128(sbase + OFF_B + rr * 256 + ((jj ^ (rr & 15)) * 16));
        }
    }
}

// ---------- fixup: exact boundary resolution for flagged tokens ----------
__global__ void fixup(const float* __restrict__ hmat, const float* __restrict__ umat,
                      const float* __restrict__ bias, float* __restrict__ out)
{
    __shared__ float sx[KDIM];
    __shared__ float sw[64];
    __shared__ float slog[64];
    __shared__ int   scand[64];
    __shared__ int   sncand, snabove;
    __shared__ unsigned long long ssel;
    __shared__ float sinv;

    const int cnt = g_cnt;
    const int tid = threadIdx.x;
    const int wrp = tid >> 5, lane = tid & 31;

    for (int i = blockIdx.x; i < cnt; i += gridDim.x) {
        const int tok = g_tok[i];
        for (int k = tid; k < EMB; k += blockDim.x) sx[k] = hmat[(size_t)tok * EMB + k];
        for (int k = tid; k < USR; k += blockDim.x) sx[EMB + k] = umat[(size_t)tok * USR + k];
        if (tid < 64) sw[tid] = g_prob[i][tid];
        if (tid == 0) { sncand = 0; snabove = 0; }
        __syncthreads();

        const float w8 = g_w89[i][0], w9 = g_w89[i][1];
        const float mid = 0.5f * (w8 + w9);
        const float B = TAU;
        if (tid < 64) {
            float wv = sw[tid];
            if (wv > mid + B) atomicAdd(&snabove, 1);
            else if (wv >= mid - B) { int p = atomicAdd(&sncand, 1); scand[p] = tid; }
        }
        __syncthreads();
        const int nc = sncand;

        // exact fp32 logits for candidate experts (one warp per candidate)
        for (int c = wrp; c < nc; c += 8) {
            int e = scand[c];
            const float* wt = &g_wt[e][0];
            float p = 0.0f;
            for (int k = lane; k < KDIM; k += 32) p += sx[k] * wt[k];
            #pragma unroll
            for (int o = 16; o > 0; o >>= 1) p += __shfl_xor_sync(0xffffffffu, p, o);
            if (lane == 0) slog[c] = p + __ldg(&bias[e]);
        }
        __syncthreads();

        if (tid == 0) {
            unsigned long long sel = 0ull;
            for (int e = 0; e < 64; e++) if (sw[e] > mid + B) sel |= 1ull << e;
            int slots = 8 - snabove;
            float pv = 3.4e38f; int pi = -1;
            for (int s = 0; s < slots; s++) {
                float bv = -3.4e38f; int bi = 999;
                for (int c = 0; c < nc; c++) {
                    int e = scand[c]; float lv = slog[c];
                    bool elig = (lv < pv) || (lv == pv && e > pi);
                    bool bett = (lv > bv) || (lv == bv && e < bi);
                    if (elig && bett) { bv = lv; bi = e; }
                }
                sel |= 1ull << bi; pv = bv; pi = bi;
            }
            float ss = 0.0f;
            for (int e = 0; e < 64; e++) if ((sel >> e) & 1) ss += sw[e];
            ssel = sel;
            sinv = 1.0f / (ss + 1e-9f);
        }
        __syncthreads();

        if (tid < 64) {
            unsigned long long sel = ssel;
            out[(size_t)tok * NEXP + tid] = ((sel >> tid) & 1) ? sw[tid] * sinv : 0.0f;
        }
        __syncthreads();
    }
}

extern "C" void kernel_launch(void* const* d_in, const int* in_sizes, int n_in,
                              void* d_out, int out_size) {
    const float* h = (const float*)d_in[0];
    const float* u = (const float*)d_in[1];
    const float* W = (const float*)d_in[2];
    const float* b = (const float*)d_in[3];
    float* out = (float*)d_out;

    prep_wt<<<(NEXP * KDIM + 255) / 256, 256>>>(W);
    prep_w<<<(NCHUNK * NEXP * RSTR + 255) / 256, 256>>>(W);

    cudaFuncSetAttribute(gate_main, cudaFuncAttributeMaxDynamicSharedMemorySize, SMEM_TOT);
    gate_main<<<NTOK / MTILE, THREADS, SMEM_TOT>>>(h, u, b, out);

    fixup<<<128, 256>>>(h, u, b, out);
}

// round 5
// speedup vs baseline: 2.0947x; 1.2840x over previous
#include <cuda_runtime.h>
#include <cuda_bf16.h>
#include <cstdint>
#include <cstddef>

#define NTOK    16384
#define EMB     2048
#define USR     256
#define KDIM    2304
#define NEXP    64
#define TOPK    8
#define KC      64
#define NCHUNK  (KDIM / KC)     // 36
#define MTILE   64
#define THREADS 256
#define TAU     1e-4f

#define RSTR    72
#define RSTRB   144

// SMEM: A [2 buf][2 part][64 x 144B] = 36864 ; B same = 36864
#define APART   9216
#define BPART   9216
#define OFF_B   (4 * APART)                 // 36864
#define SMEM_TOT (OFF_B + 4 * BPART)        // 73728

__device__ __align__(16) __nv_bfloat16 g_wpack[NCHUNK][2][NEXP * RSTR];
__device__ __align__(16) float g_wt[NEXP][KDIM];
#define FIXCAP NTOK
__device__ int   g_cnt;
__device__ int   g_tok[FIXCAP];
__device__ float g_w89[FIXCAP][2];
__device__ float g_prob[FIXCAP][NEXP];

// ---------- helpers ----------
__device__ __forceinline__ uint32_t smem_u32(const void* p) {
    uint32_t a;
    asm("{ .reg .u64 t; cvta.to.shared.u64 t, %1; cvt.u32.u64 %0, t; }" : "=r"(a) : "l"(p));
    return a;
}
__device__ __forceinline__ uint32_t cvt_bf16x2(float hi, float lo) {
    uint32_t r;
    asm("cvt.rn.bf16x2.f32 %0, %1, %2;" : "=r"(r) : "f"(hi), "f"(lo));
    return r;
}
__device__ __forceinline__ void sts64(uint32_t a, uint32_t r0, uint32_t r1) {
    asm volatile("st.shared.v2.b32 [%0], {%1, %2};" :: "r"(a), "r"(r0), "r"(r1) : "memory");
}
__device__ __forceinline__ void sts128(uint32_t a, uint4 v) {
    asm volatile("st.shared.v4.b32 [%0], {%1,%2,%3,%4};" :: "r"(a), "r"(v.x), "r"(v.y), "r"(v.z), "r"(v.w) : "memory");
}
__device__ __forceinline__ uint4 lds128(uint32_t a) {
    uint4 v;
    asm volatile("ld.shared.v4.b32 {%0,%1,%2,%3}, [%4];" : "=r"(v.x), "=r"(v.y), "=r"(v.z), "=r"(v.w) : "r"(a));
    return v;
}
__device__ __forceinline__ void ldsm4(uint32_t* r, uint32_t addr) {
    asm volatile("ldmatrix.sync.aligned.m8n8.x4.shared.b16 {%0,%1,%2,%3}, [%4];"
                 : "=r"(r[0]), "=r"(r[1]), "=r"(r[2]), "=r"(r[3]) : "r"(addr));
}
__device__ __forceinline__ void mma16816(float* d, const uint32_t* a, uint32_t b0, uint32_t b1) {
    asm volatile("mma.sync.aligned.m16n8k16.row.col.f32.bf16.bf16.f32 "
                 "{%0,%1,%2,%3}, {%4,%5,%6,%7}, {%8,%9}, {%0,%1,%2,%3};"
                 : "+f"(d[0]), "+f"(d[1]), "+f"(d[2]), "+f"(d[3])
                 : "r"(a[0]), "r"(a[1]), "r"(a[2]), "r"(a[3]), "r"(b0), "r"(b1));
}
__device__ __forceinline__ void cpasync16(uint32_t dst, const void* src) {
    asm volatile("cp.async.cg.shared.global [%0], [%1], 16;" :: "r"(dst), "l"(src));
}

// ---------- combined prep ----------
__global__ void prep(const float* __restrict__ W) {
    int idx = blockIdx.x * blockDim.x + threadIdx.x;
    if (idx == 0) g_cnt = 0;
    if (idx < NCHUNK * NEXP * RSTR) {
        int c   = idx / (NEXP * RSTR);
        int rem = idx % (NEXP * RSTR);
        int n   = rem / RSTR;
        int kk  = rem % RSTR;
        float v = (kk < KC) ? W[(size_t)(c * KC + kk) * NEXP + n] : 0.0f;
        __nv_bfloat16 hi = __float2bfloat16(v);
        __nv_bfloat16 lo = __float2bfloat16(v - __bfloat162float(hi));
        g_wpack[c][0][n * RSTR + kk] = hi;
        g_wpack[c][1][n * RSTR + kk] = lo;
    }
    if (idx < NEXP * KDIM) {
        int e = idx / KDIM;
        int k = idx % KDIM;
        g_wt[e][k] = W[(size_t)k * NEXP + e];
    }
}

// ---------- main ----------
__global__ __launch_bounds__(THREADS, 2)
void gate_main(const float* __restrict__ hmat, const float* __restrict__ umat,
               const float* __restrict__ bias, float* __restrict__ out)
{
    extern __shared__ char smem[];
    const uint32_t sbase = smem_u32(smem);
    const int tid  = threadIdx.x;
    const int wid  = tid >> 5;
    const int lane = tid & 31;
    const int wr   = wid & 1;       // m 32-block (0..1)
    const int wc   = wid >> 1;      // n 16-block (0..3)
    const int tok0 = blockIdx.x * MTILE;

    // staging: row r (0..63), 16-col quarter
    const int r  = tid >> 2;
    const int k0 = (tid & 3) * 16;

    float4 xr[4];

    auto ldgA = [&](int c) {
        const int kb = c * KC;
        const float* src = (kb < EMB)
            ? hmat + (size_t)(tok0 + r) * EMB + kb + k0
            : umat + (size_t)(tok0 + r) * USR + (kb - EMB) + k0;
        #pragma unroll
        for (int j = 0; j < 4; j++) xr[j] = __ldg((const float4*)src + j);
    };
    auto cpB = [&](int c, int buf) {
        const char* src = (const char*)&g_wpack[c][0][0];
        const uint32_t dst = sbase + OFF_B + buf * (2 * BPART);
        #pragma unroll
        for (int i = tid; i < 2 * BPART / 16; i += THREADS)
            cpasync16(dst + i * 16, src + i * 16);
        asm volatile("cp.async.commit_group;");
    };
    auto convA = [&](int buf) {
        const uint32_t ah = sbase + (buf * 2 + 0) * APART;
        const uint32_t al = sbase + (buf * 2 + 1) * APART;
        #pragma unroll
        for (int j = 0; j < 4; j++) {
            float4 v = xr[j];
            uint32_t hi01 = cvt_bf16x2(v.y, v.x);
            uint32_t hi23 = cvt_bf16x2(v.w, v.z);
            float h0 = __uint_as_float(hi01 << 16);
            float h1 = __uint_as_float(hi01 & 0xFFFF0000u);
            float h2 = __uint_as_float(hi23 << 16);
            float h3 = __uint_as_float(hi23 & 0xFFFF0000u);
            uint32_t lo01 = cvt_bf16x2(v.y - h1, v.x - h0);
            uint32_t lo23 = cvt_bf16x2(v.w - h3, v.z - h2);
            unsigned off = (unsigned)(r * RSTRB + (k0 + 4 * j) * 2);
            sts64(ah + off, hi01, hi23);
            sts64(al + off, lo01, lo23);
        }
    };

    float acc[2][2][4];
    #pragma unroll
    for (int mt = 0; mt < 2; mt++)
        #pragma unroll
        for (int nt = 0; nt < 2; nt++)
            #pragma unroll
            for (int q = 0; q < 4; q++) acc[mt][nt][q] = 0.0f;

    const int arow = wr * 32 + ((lane >> 3) & 1) * 8 + (lane & 7);
    const int aoff = arow * RSTRB + (lane >> 4) * 16;
    const int bn   = wc * 16 + (lane >> 4) * 8 + (lane & 7);
    const int boff = bn * RSTRB + ((lane >> 3) & 1) * 16;

    ldgA(0);
    cpB(0, 0);

    for (int T = 0; T < NCHUNK; T++) {
        const int buf = T & 1;
        convA(buf);
        if (T + 1 < NCHUNK) ldgA(T + 1);
        asm volatile("cp.async.wait_group 0;");
        __syncthreads();
        if (T + 1 < NCHUNK) cpB(T + 1, buf ^ 1);

        const uint32_t ah = sbase + (buf * 2 + 0) * APART;
        const uint32_t al = sbase + (buf * 2 + 1) * APART;
        const uint32_t bh = sbase + OFF_B + buf * (2 * BPART);
        const uint32_t bl = bh + BPART;

        #pragma unroll
        for (int kt = 0; kt < 4; kt++) {
            const int kb = kt * 32;             // bytes = 16 k-cols
            uint32_t Ah[2][4], Al[2][4], Bh[4], Bl[4];
            ldsm4(Ah[0], ah + aoff + kb);
            ldsm4(Ah[1], ah + aoff + kb + 16 * RSTRB);
            ldsm4(Al[0], al + aoff + kb);
            ldsm4(Al[1], al + aoff + kb + 16 * RSTRB);
            ldsm4(Bh, bh + boff + kb);
            ldsm4(Bl, bl + boff + kb);
            #pragma unroll
            for (int mt = 0; mt < 2; mt++) {
                mma16816(acc[mt][0], Ah[mt], Bh[0], Bh[1]);
                mma16816(acc[mt][1], Ah[mt], Bh[2], Bh[3]);
                mma16816(acc[mt][0], Ah[mt], Bl[0], Bl[1]);
                mma16816(acc[mt][1], Ah[mt], Bl[2], Bl[3]);
                mma16816(acc[mt][0], Al[mt], Bh[0], Bh[1]);
                mma16816(acc[mt][1], Al[mt], Bh[2], Bh[3]);
            }
        }
        __syncthreads();
    }

    // ---- epilogue: accums -> SMEM logits [64][68] ----
    const int t4r = lane >> 2;
    const int t4c = (lane & 3) * 2;
    #pragma unroll
    for (int mt = 0; mt < 2; mt++)
        #pragma unroll
        for (int nt = 0; nt < 2; nt++) {
            int row = wr * 32 + mt * 16 + t4r;
            int col = wc * 16 + nt * 8 + t4c;
            uint32_t a0 = sbase + (row * 68 + col) * 4;
            uint32_t a1 = sbase + ((row + 8) * 68 + col) * 4;
            sts64(a0, __float_as_uint(acc[mt][nt][0]), __float_as_uint(acc[mt][nt][1]));
            sts64(a1, __float_as_uint(acc[mt][nt][2]), __float_as_uint(acc[mt][nt][3]));
        }
    __syncthreads();

    if (tid < MTILE) {
        const int m = tid;
        float v[64];
        float mx = -3.4e38f;
        #pragma unroll
        for (int i = 0; i < 64; i++) {
            float lv;
            asm volatile("ld.shared.f32 %0, [%1];" : "=f"(lv) : "r"(sbase + (m * 68 + i) * 4));
            v[i] = lv + __ldg(&bias[i]);
            mx = fmaxf(mx, v[i]);
        }
        float s = 0.0f;
        #pragma unroll
        for (int i = 0; i < 64; i++) { v[i] = __expf(v[i] - mx); s += v[i]; }
        const float invs = 1.0f / s;
        #pragma unroll
        for (int i = 0; i < 64; i++) v[i] *= invs;

        float prevV = 3.4e38f; int prevI = -1;
        float ssum = 0.0f;
        unsigned long long msk = 0ull;
        #pragma unroll 1
        for (int it = 0; it < TOPK; it++) {
            float bv = -1.0f; int bi = 64;
            #pragma unroll
            for (int i = 0; i < 64; i++) {
                bool elig = (v[i] < prevV) || (v[i] == prevV && i > prevI);
                bool bett = (v[i] > bv) || (v[i] == bv && i < bi);
                if (elig && bett) { bv = v[i]; bi = i; }
            }
            ssum += bv; prevV = bv; prevI = bi; msk |= 1ull << bi;
        }
        float bv9 = -1.0f;
        {
            int bi9 = 64;
            #pragma unroll
            for (int i = 0; i < 64; i++) {
                bool elig = (v[i] < prevV) || (v[i] == prevV && i > prevI);
                bool bett = (v[i] > bv9) || (v[i] == bv9 && i < bi9);
                if (elig && bett) { bv9 = v[i]; bi9 = i; }
            }
        }
        if (prevV - bv9 < TAU) {
            int slot = atomicAdd(&g_cnt, 1);
            g_tok[slot] = tok0 + m;
            g_w89[slot][0] = prevV;
            g_w89[slot][1] = bv9;
            #pragma unroll
            for (int i = 0; i < 64; i++) g_prob[slot][i] = v[i];
        }

        const float inv = 1.0f / (ssum + 1e-9f);
        const uint32_t rowb = sbase + OFF_B + m * 256;
        #pragma unroll
        for (int j = 0; j < 16; j++) {
            float4 o;
            o.x = ((msk >> (4 * j + 0)) & 1) ? v[4 * j + 0] * inv : 0.0f;
            o.y = ((msk >> (4 * j + 1)) & 1) ? v[4 * j + 1] * inv : 0.0f;
            o.z = ((msk >> (4 * j + 2)) & 1) ? v[4 * j + 2] * inv : 0.0f;
            o.w = ((msk >> (4 * j + 3)) & 1) ? v[4 * j + 3] * inv : 0.0f;
            uint4 u4 = make_uint4(__float_as_uint(o.x), __float_as_uint(o.y),
                                  __float_as_uint(o.z), __float_as_uint(o.w));
            sts128(rowb + ((j ^ (m & 15)) * 16), u4);
        }
    }
    __syncthreads();

    {
        uint4* og = (uint4*)(out + (size_t)tok0 * NEXP);
        #pragma unroll
        for (int i = 0; i < 4; i++) {
            int f  = tid + THREADS * i;          // 1024 float4s per CTA
            int rr = f >> 4, jj = f & 15;
            og[f] = lds128(sbase + OFF_B + rr * 256 + ((jj ^ (rr & 15)) * 16));
        }
    }
}

// ---------- fixup: one flagged token per block, MLP-unrolled exact dots ----------
__global__ void fixup(const float* __restrict__ hmat, const float* __restrict__ umat,
                      const float* __restrict__ bias, float* __restrict__ out)
{
    __shared__ float sw[64];
    __shared__ float slog[64];
    __shared__ int   scand[64];
    __shared__ int   sncand, snabove;
    __shared__ unsigned long long ssel;
    __shared__ float sinv;

    const int cnt = g_cnt;
    const int tid = threadIdx.x;
    const int wrp = tid >> 5, lane = tid & 31;

    for (int i = blockIdx.x; i < cnt; i += gridDim.x) {
        const int tok = g_tok[i];
        if (tid < 64) sw[tid] = g_prob[i][tid];
        if (tid == 0) { sncand = 0; snabove = 0; }
        __syncthreads();

        const float mid = 0.5f * (g_w89[i][0] + g_w89[i][1]);
        if (tid < 64) {
            float wv = sw[tid];
            if (wv > mid + TAU) atomicAdd(&snabove, 1);
            else if (wv >= mid - TAU) { int p = atomicAdd(&sncand, 1); scand[p] = tid; }
        }
        __syncthreads();
        const int nc = sncand;

        // one warp per candidate: exact fp32 dot, float4 loads, deep MLP
        for (int c = wrp; c < nc; c += 8) {
            int e = scand[c];
            const float4* x4h = (const float4*)(hmat + (size_t)tok * EMB);
            const float4* x4u = (const float4*)(umat + (size_t)tok * USR);
            const float4* w4  = (const float4*)&g_wt[e][0];
            float p = 0.0f;
            #pragma unroll
            for (int j = 0; j < 16; j++) {          // EMB: 512 float4
                float4 xv = __ldg(x4h + lane + 32 * j);
                float4 wv = __ldg(w4  + lane + 32 * j);
                p += xv.x * wv.x + xv.y * wv.y + xv.z * wv.z + xv.w * wv.w;
            }
            #pragma unroll
            for (int j = 0; j < 2; j++) {           // USR: 64 float4
                float4 xv = __ldg(x4u + lane + 32 * j);
                float4 wv = __ldg(w4 + 512 + lane + 32 * j);
                p += xv.x * wv.x + xv.y * wv.y + xv.z * wv.z + xv.w * wv.w;
            }
            #pragma unroll
            for (int o = 16; o > 0; o >>= 1) p += __shfl_xor_sync(0xffffffffu, p, o);
            if (lane == 0) slog[c] = p + __ldg(&bias[e]);
        }
        __syncthreads();

        if (tid == 0) {
            unsigned long long sel = 0ull;
            for (int e = 0; e < 64; e++) if (sw[e] > mid + TAU) sel |= 1ull << e;
            int slots = 8 - snabove;
            float pv = 3.4e38f; int pi = -1;
            for (int s = 0; s < slots; s++) {
                float bv = -3.4e38f; int bi = 999;
                for (int c = 0; c < nc; c++) {
                    int e = scand[c]; float lv = slog[c];
                    bool elig = (lv < pv) || (lv == pv && e > pi);
                    bool bett = (lv > bv) || (lv == bv && e < bi);
                    if (elig && bett) { bv = lv; bi = e; }
                }
                sel |= 1ull << bi; pv = bv; pi = bi;
            }
            float ss = 0.0f;
            for (int e = 0; e < 64; e++) if ((sel >> e) & 1) ss += sw[e];
            ssel = sel;
            sinv = 1.0f / (ss + 1e-9f);
        }
        __syncthreads();

        if (tid < 64)
            out[(size_t)tok * NEXP + tid] = ((ssel >> tid) & 1) ? sw[tid] * sinv : 0.0f;
        __syncthreads();
    }
}

extern "C" void kernel_launch(void* const* d_in, const int* in_sizes, int n_in,
                              void* d_out, int out_size) {
    const float* h = (const float*)d_in[0];
    const float* u = (const float*)d_in[1];
    const float* W = (const float*)d_in[2];
    const float* b = (const float*)d_in[3];
    float* out = (float*)d_out;

    prep<<<(NCHUNK * NEXP * RSTR + 255) / 256, 256>>>(W);

    cudaFuncSetAttribute(gate_main, cudaFuncAttributeMaxDynamicSharedMemorySize, SMEM_TOT);
    gate_main<<<NTOK / MTILE, THREADS, SMEM_TOT>>>(h, u, b, out);

    fixup<<<1024, 256>>>(h, u, b, out);
}